// round 4
// baseline (speedup 1.0000x reference)
#include <cuda_runtime.h>
#include <cuda_bf16.h>

// LIF scan, chunk-parallel with cold-start warm-up.
//   i_t = LEAK_I*i_{t-1} + w*x_t
//   v_t = LEAK_V*v_{t-1}*(1-s_{t-1}) + i_t
//   s_t = (v_t - 1 > 0)
// State memory decays (0.9^t for v, (6/7)^t for i) and every spike resets v
// exactly, so a chunk warmed from (0,0,0) over W steps converges to the true
// trajectory within 0.9^W relative (2e-12 at W=256); any spike during warm-up
// resynchronizes v exactly. Arithmetic replicates the reference op-for-op in
// f32 (no FMA contraction); (1-s) with s in {0,1} becomes an exact select.
//
// R1: L=512/W=512, 16K threads -> latency-bound (occ 5.6%, issue 6.8%, DRAM 16%).
// R2-R4: L=128/W=256 -> 65K threads (4x parallelism), 1.5x redundant compute.
//   R2/R3 were broker infra failures (kernel never ran). R4: block 256->128
//   (512 CTAs, ~3.5 waves on 148 SMs) to smooth the tail wave; same occupancy.

#define CHUNK_L 128
#define WARM_W  256

__device__ __forceinline__ void lif_step(float xt, float w, float LI, float LV,
                                         float& s, float& v, float& i) {
    float wx = __fmul_rn(w, xt);
    i = __fadd_rn(__fmul_rn(LI, i), wx);
    float lv = __fmul_rn(LV, v);
    lv = (s != 0.0f) ? 0.0f : lv;       // exact: (LV*v)*(1-s) with s in {0,1}
    v = __fadd_rn(lv, i);
    s = (v > 1.0f) ? 1.0f : 0.0f;       // Heaviside(v - 1) with strict >
}

__global__ void __launch_bounds__(128)
lif_scan_kernel(const float* __restrict__ x,
                const float* __restrict__ state0,
                const float* __restrict__ wptr,
                float* __restrict__ out,
                int T, int write_states) {
    const float LI = (float)(1.0 - 1.0 / 7.0);    // 6/7
    const float LV = (float)(1.0 - 1.0 / 10.0);   // 0.9

    long long nchunks = ((long long)T + CHUNK_L - 1) / CHUNK_L;
    long long c = (long long)blockIdx.x * blockDim.x + threadIdx.x;
    if (c >= nchunks) return;

    long long start = c * CHUNK_L;
    long long end = start + CHUNK_L;
    if (end > T) end = T;

    float w = wptr[0];
    float s, v, i;

    if (c == 0) {
        s = state0[0]; v = state0[1]; i = state0[2];
    } else {
        // Cold-start warm-up over the preceding W steps (clamped at 0).
        s = 0.0f; v = 0.0f; i = 0.0f;
        long long wstart = start - WARM_W;
        if (wstart < 0) wstart = 0;           // only if CHUNK_L < WARM_W and c small
        int wn = (int)(start - wstart);
        const float4* xw = (const float4*)(x + wstart);
        #pragma unroll 8
        for (int j = 0; j < wn / 4; ++j) {
            float4 q = xw[j];
            lif_step(q.x, w, LI, LV, s, v, i);
            lif_step(q.y, w, LI, LV, s, v, i);
            lif_step(q.z, w, LI, LV, s, v, i);
            lif_step(q.w, w, LI, LV, s, v, i);
        }
    }

    float* outs = out + start;                       // outputs[t]
    float* outv = out + (long long)T + 3 * start;    // states[t, 0..2]
    int L  = (int)(end - start);
    int L4 = L & ~3;

    // Vectorized main loop: float4 x-loads, float4 stores. All base offsets are
    // multiples of 4 floats (start % 128 == 0, 3*start % 4 == 0).
    #pragma unroll 4
    for (int j = 0; j < L4; j += 4) {
        float4 q = *(const float4*)(x + start + j);
        float4 sb, a, b, cv;
        lif_step(q.x, w, LI, LV, s, v, i); sb.x = s; a.x  = s; a.y  = v; a.z  = i;
        lif_step(q.y, w, LI, LV, s, v, i); sb.y = s; a.w  = s; b.x  = v; b.y  = i;
        lif_step(q.z, w, LI, LV, s, v, i); sb.z = s; b.z  = s; b.w  = v; cv.x = i;
        lif_step(q.w, w, LI, LV, s, v, i); sb.w = s; cv.y = s; cv.z = v; cv.w = i;

        *(float4*)(outs + j) = sb;
        if (write_states) {
            float4* ov = (float4*)(outv + 3 * j);
            ov[0] = a; ov[1] = b; ov[2] = cv;
        }
    }
    // Scalar tail (only if T not a multiple of 4 within the last chunk)
    for (int j = L4; j < L; ++j) {
        lif_step(x[start + j], w, LI, LV, s, v, i);
        outs[j] = s;
        if (write_states) {
            outv[3 * j + 0] = s;
            outv[3 * j + 1] = v;
            outv[3 * j + 2] = i;
        }
    }
}

extern "C" void kernel_launch(void* const* d_in, const int* in_sizes, int n_in,
                              void* d_out, int out_size) {
    const float* x  = (const float*)d_in[0];   // (T, 1) float32
    const float* st = (const float*)d_in[1];   // (3, 1) float32 [s, v, i]
    const float* w  = (const float*)d_in[2];   // (1, 1) float32
    float* out = (float*)d_out;                // [outputs (T) | states (3T)]

    int T = in_sizes[0];
    int write_states = ((long long)out_size >= 4LL * T) ? 1 : 0;

    long long nchunks = ((long long)T + CHUNK_L - 1) / CHUNK_L;
    int threads = 128;
    int blocks = (int)((nchunks + threads - 1) / threads);
    lif_scan_kernel<<<blocks, threads>>>(x, st, w, out, T, write_states);
}

// round 6
// speedup vs baseline: 1.4924x; 1.4924x over previous
#include <cuda_runtime.h>
#include <cuda_bf16.h>

// LIF scan, chunk-parallel with cold-start warm-up, FULLY COALESCED via
// warp-local SMEM staging.
//
//   i_t = LEAK_I*i_{t-1} + w*x_t
//   v_t = LEAK_V*v_{t-1}*(1-s_{t-1}) + i_t
//   s_t = (v_t - 1 > 0)
//
// A chunk warmed from zeros over W=256 steps matches the true trajectory to
// 0.9^256 ~ 2e-12 (validated R4: rel_err 1.08e-7, identical to exact-W runs);
// warm-up spikes resync v bitwise. Chunks whose warm window reaches t=0 warm
// from the true initial state (exact). Arithmetic replicates the reference
// op-for-op in f32; (1-s) with s in {0,1} becomes an exact select.
//
// R4 lesson: per-thread-sequential layout -> 32 L1 wavefronts per warp LDG/STG
// (512B lane stride). L1tex pipe (47%) was the binder; occupancy didn't help.
// R5/R6: warp owns 32 consecutive chunks (lane=chunk, L=64).
//   - x window (contiguous 9.2KB) loaded coalesced into pitch-33 SMEM once;
//     warm-up re-reads hit SMEM (x DRAM traffic 1.125x).
//   - outputs/states staged per 32-step tile in SMEM (conflict-free pitches),
//     flushed with coalesced STG.32 (1 wavefront / 128B).
//   (R5 bench was a broker infra failure; unchanged resubmit.)

#define CHUNK_L 64
#define WARM_W  256
#define LANES   32
#define WPB     4                                  // warps per block
#define NTHREADS (WPB * LANES)

#define WIN_FLOATS (LANES * CHUNK_L + WARM_W)      // 2304
#define WIN_ROWS   (WIN_FLOATS / 32)               // 72
#define XPITCH 33
#define X_WORDS (WIN_ROWS * XPITCH)                // 2376
#define OPITCH 33
#define O_WORDS (LANES * OPITCH)                   // 1056
#define SPITCH 99
#define S_WORDS (LANES * SPITCH)                   // 3168
#define WARP_WORDS (X_WORDS + O_WORDS + S_WORDS)   // 6600
#define BLOCK_SMEM (WARP_WORDS * WPB * 4)          // 105600 bytes

__device__ __forceinline__ void lif_step(float xt, float w, float LI, float LV,
                                         float& s, float& v, float& i) {
    float wx = __fmul_rn(w, xt);
    i = __fadd_rn(__fmul_rn(LI, i), wx);
    float lv = __fmul_rn(LV, v);
    lv = (s != 0.0f) ? 0.0f : lv;       // exact: (LV*v)*(1-s) with s in {0,1}
    v = __fadd_rn(lv, i);
    s = (v > 1.0f) ? 1.0f : 0.0f;       // Heaviside(v - 1) with strict >
}

__global__ void __launch_bounds__(NTHREADS, 2)
lif_scan_kernel(const float* __restrict__ x,
                const float* __restrict__ state0,
                const float* __restrict__ wptr,
                float* __restrict__ out,
                int T, int write_states) {
    extern __shared__ float sm[];
    const float LI = (float)(1.0 - 1.0 / 7.0);    // 6/7
    const float LV = (float)(1.0 - 1.0 / 10.0);   // 0.9

    const int lane = threadIdx.x & 31;
    const int warp = threadIdx.x >> 5;
    float* xs = sm + warp * WARP_WORDS;   // x window, pitch 33
    float* os = xs + X_WORDS;             // outputs tile, pitch 33
    float* ss = os + O_WORDS;             // states tile,  pitch 99

    const long long nchunks = ((long long)T + CHUNK_L - 1) / CHUNK_L;
    const long long wid = (long long)blockIdx.x * WPB + warp;
    const long long cb  = wid * LANES;            // first chunk of this warp
    if (cb >= nchunks) return;                    // warp-uniform exit

    const long long B = cb * CHUNK_L - WARM_W;    // window base (may be < 0)
    const float w = wptr[0];

    // ---- coalesced fill of x window into SMEM ----
    for (int q = lane; q < WIN_FLOATS / 4; q += LANES) {
        long long t = B + (long long)q * 4;       // multiple of 4
        float4 val = make_float4(0.f, 0.f, 0.f, 0.f);
        if (t >= 0) {
            if (t + 3 < (long long)T) {
                val = *(const float4*)(x + t);
            } else {
                if (t + 0 < T) val.x = x[t + 0];
                if (t + 1 < T) val.y = x[t + 1];
                if (t + 2 < T) val.z = x[t + 2];
            }
        }
        int f = q * 4, row = f >> 5, col = f & 31;
        float* p = xs + row * XPITCH + col;       // conflict-free (bank = row+4m+k)
        p[0] = val.x; p[1] = val.y; p[2] = val.z; p[3] = val.w;
    }
    __syncwarp();

    // ---- per-lane chunk state ----
    const long long c = cb + lane;                // this lane's chunk
    const long long start = c * CHUNK_L;
    float s, v, i;
    long long wlen;
    if (start - WARM_W >= 0) {
        s = 0.f; v = 0.f; i = 0.f;  wlen = WARM_W;
    } else {
        s = state0[0]; v = state0[1]; i = state0[2];  wlen = start; // exact warm from t=0
    }

    // ---- warm-up from SMEM (row-aligned: wlen and offsets are multiples of 32) ----
    {
        int o0 = (int)(start - wlen - B);         // buffer float offset, mult of 32
        int wrows = (int)(wlen >> 5);
        for (int r = 0; r < wrows; ++r) {
            const float* p = xs + (unsigned)((o0 >> 5) + r) * XPITCH;
            #pragma unroll
            for (int j = 0; j < 32; ++j)
                lif_step(p[j], w, LI, LV, s, v, i);
        }
    }

    // ---- main: 2 tiles of 32 steps, stage -> coalesced flush ----
    const int mo = (int)(start - B);              // = lane*64 + 256, mult of 32
    float* orow = os + lane * OPITCH;
    float* srow = ss + lane * SPITCH;
    const long long T4 = 4LL * T;

    for (int tile = 0; tile < 2; ++tile) {
        const float* p = xs + (unsigned)((mo >> 5) + tile) * XPITCH;
        #pragma unroll
        for (int j = 0; j < 32; ++j) {
            lif_step(p[j], w, LI, LV, s, v, i);
            orow[j] = s;
            srow[3 * j + 0] = s;
            srow[3 * j + 1] = v;
            srow[3 * j + 2] = i;
        }
        __syncwarp();

        // outputs: chunk r segment = [ (cb+r)*64 + tile*32 , +32 )
        long long obase = cb * CHUNK_L + (long long)tile * 32 + lane;
        #pragma unroll 4
        for (int r = 0; r < LANES; ++r) {
            long long go = obase + (long long)r * CHUNK_L;
            if (go < (long long)T) out[go] = os[r * OPITCH + lane];
        }
        // states: chunk r segment = T + (cb+r)*192 + tile*96 + [0,96)
        if (write_states) {
            long long sbase = (long long)T + cb * (CHUNK_L * 3)
                            + (long long)tile * 96 + lane;
            #pragma unroll 4
            for (int r = 0; r < LANES; ++r) {
                long long gb = sbase + (long long)r * (CHUNK_L * 3);
                const float* sr = ss + r * SPITCH;
                if (gb      < T4) out[gb]      = sr[lane];
                if (gb + 32 < T4) out[gb + 32] = sr[32 + lane];
                if (gb + 64 < T4) out[gb + 64] = sr[64 + lane];
            }
        }
        __syncwarp();
    }
}

extern "C" void kernel_launch(void* const* d_in, const int* in_sizes, int n_in,
                              void* d_out, int out_size) {
    const float* x  = (const float*)d_in[0];   // (T, 1) float32
    const float* st = (const float*)d_in[1];   // (3, 1) float32 [s, v, i]
    const float* w  = (const float*)d_in[2];   // (1, 1) float32
    float* out = (float*)d_out;                // [outputs (T) | states (3T)]

    int T = in_sizes[0];
    int write_states = ((long long)out_size >= 4LL * T) ? 1 : 0;

    cudaFuncSetAttribute(lif_scan_kernel,
                         cudaFuncAttributeMaxDynamicSharedMemorySize, BLOCK_SMEM);

    long long nchunks = ((long long)T + CHUNK_L - 1) / CHUNK_L;
    long long nwarps  = (nchunks + LANES - 1) / LANES;
    int blocks = (int)((nwarps + WPB - 1) / WPB);
    lif_scan_kernel<<<blocks, NTHREADS, BLOCK_SMEM>>>(x, st, w, out, T, write_states);
}

// round 8
// speedup vs baseline: 2.7843x; 1.8657x over previous
#include <cuda_runtime.h>
#include <cuda_bf16.h>

// LIF scan, chunk-parallel with cold-start warm-up, coalesced SMEM staging,
// vectorized (4-step groups, LDS.128/STS.128/STG.128).
//
//   i_t = LEAK_I*i_{t-1} + w*x_t
//   v_t = LEAK_V*v_{t-1}*(1-s_{t-1}) + i_t
//   s_t = (v_t - 1 > 0)        [ (v>1) == (v-1>0) exactly in f32 ]
//
// Warm-up: chunk warmed from zeros over W=128 steps; i converges at (6/7)^128
// ~3e-9 and spikes (every ~4 steps) resync v bitwise once i is converged.
// Chunks with start <= W warm exactly from state0. Arithmetic replicates the
// reference op-for-op in f32; (1-s) with s in {0,1} gates exactly.
//
// R6 lesson: coalescing fixed L1 (47->31%) but issue stuck at 29% -> ~130
// cyc/step: unhoisted scalar LDS in the v-chain (regs=32), 5 scalar MIO ops
// per step, and 4x warm redundancy. R7/R8: W=128 (192 serial steps/warp),
// float4 x loads hoisted ahead of 4-step groups, float4 staging/flush.
// (R7 bench was a broker infra failure; unchanged resubmit.)

#define CHUNK_L 64
#define WARM_W  128
#define LANES   32
#define WPB     4
#define NTHREADS (WPB * LANES)

#define WIN_FLOATS (LANES * CHUNK_L + WARM_W)      // 2176
#define WIN_ROWS   (WIN_FLOATS / 32)               // 68
#define XPITCH 36
#define X_WORDS (WIN_ROWS * XPITCH)                // 2448
#define OPITCH 36
#define O_WORDS (LANES * OPITCH)                   // 1152
#define SPITCH 100
#define S_WORDS (LANES * SPITCH)                   // 3200
#define WARP_WORDS (X_WORDS + O_WORDS + S_WORDS)   // 6800
#define BLOCK_SMEM (WARP_WORDS * WPB * 4)          // 108800 B -> 2 CTAs/SM

__device__ __forceinline__ void lif_step(float xt, float w, float LI, float LV,
                                         float& s, float& v, float& i) {
    float wx = __fmul_rn(w, xt);
    i = __fadd_rn(__fmul_rn(LI, i), wx);
    float km = __fsub_rn(1.0f, s);                    // exact: s in {0,1}
    float lv = __fmul_rn(__fmul_rn(LV, v), km);       // exact gating (x1 or x0)
    v = __fadd_rn(lv, i);
    s = (v > 1.0f) ? 1.0f : 0.0f;                     // FSETP+FSEL (pred-as-data)
}

__global__ void __launch_bounds__(NTHREADS, 2)
lif_scan_kernel(const float* __restrict__ x,
                const float* __restrict__ state0,
                const float* __restrict__ wptr,
                float* __restrict__ out,
                int T, int write_states) {
    extern __shared__ float sm[];
    const float LI = (float)(1.0 - 1.0 / 7.0);    // 6/7
    const float LV = (float)(1.0 - 1.0 / 10.0);   // 0.9

    const int lane = threadIdx.x & 31;
    const int warp = threadIdx.x >> 5;
    float* xs = sm + warp * WARP_WORDS;   // x window,     pitch 36
    float* os = xs + X_WORDS;             // outputs tile, pitch 36
    float* ss = os + O_WORDS;             // states tile,  pitch 100

    const long long nchunks = ((long long)T + CHUNK_L - 1) / CHUNK_L;
    const long long wid = (long long)blockIdx.x * WPB + warp;
    const long long cb  = wid * LANES;            // first chunk of this warp
    if (cb >= nchunks) return;                    // warp-uniform

    const long long B = cb * CHUNK_L - WARM_W;    // window base
    const float w = wptr[0];

    // Fast path: full interior warp (window + all 32 chunks in-bounds).
    const bool fastw = (B >= 0) && ((cb + LANES) * CHUNK_L <= (long long)T);

    if (fastw) {
        // ---- coalesced window fill: 17 LDG.128 rounds, MLP-batched ----
        {
            const float4* g = (const float4*)(x + B);
            #pragma unroll
            for (int it = 0; it < WIN_FLOATS / 128; ++it) {
                int q = it * 32 + lane;
                float4 val = g[q];
                int row = q >> 3, col = (q & 7) * 4;
                *(float4*)(xs + row * XPITCH + col) = val;
            }
        }
        __syncwarp();

        float s = 0.f, v = 0.f, i = 0.f;

        // ---- warm-up: rows 2*lane .. 2*lane+3 (128 steps) ----
        #pragma unroll
        for (int r = 0; r < WARM_W / 32; ++r) {
            const float* p = xs + (2 * lane + r) * XPITCH;
            #pragma unroll
            for (int jj = 0; jj < 32; jj += 4) {
                float4 q = *(const float4*)(p + jj);
                lif_step(q.x, w, LI, LV, s, v, i);
                lif_step(q.y, w, LI, LV, s, v, i);
                lif_step(q.z, w, LI, LV, s, v, i);
                lif_step(q.w, w, LI, LV, s, v, i);
            }
        }

        // ---- main: 2 tiles of 32 steps ----
        float* orow = os + lane * OPITCH;
        float* srow = ss + lane * SPITCH;
        #pragma unroll
        for (int tile = 0; tile < 2; ++tile) {
            const float* p = xs + (2 * lane + WARM_W / 32 + tile) * XPITCH;
            #pragma unroll
            for (int jj = 0; jj < 32; jj += 4) {
                float4 q = *(const float4*)(p + jj);
                float4 o4, st0, st1, st2;
                lif_step(q.x, w, LI, LV, s, v, i); o4.x = s; st0.x = s; st0.y = v; st0.z = i;
                lif_step(q.y, w, LI, LV, s, v, i); o4.y = s; st0.w = s; st1.x = v; st1.y = i;
                lif_step(q.z, w, LI, LV, s, v, i); o4.z = s; st1.z = s; st1.w = v; st2.x = i;
                lif_step(q.w, w, LI, LV, s, v, i); o4.w = s; st2.y = s; st2.z = v; st2.w = i;
                *(float4*)(orow + jj) = o4;
                float* sp = srow + 3 * jj;
                *(float4*)(sp)     = st0;
                *(float4*)(sp + 4) = st1;
                *(float4*)(sp + 8) = st2;
            }
            __syncwarp();

            // outputs flush: 8 STG.128 rounds (4 chunks per round, coalesced)
            {
                long long obase = cb * CHUNK_L + (long long)tile * 32;
                int sub = lane >> 3;          // 0..3
                int off = (lane & 7) * 4;     // 0..28
                #pragma unroll
                for (int g = 0; g < 8; ++g) {
                    int rr = g * 4 + sub;
                    float4 vv = *(const float4*)(os + rr * OPITCH + off);
                    *(float4*)(out + obase + (long long)rr * CHUNK_L + off) = vv;
                }
            }
            // states flush: 32 STG.128 rounds (24 active lanes, 96 floats/chunk)
            if (write_states && lane < 24) {
                long long sbase = (long long)T + cb * (3 * CHUNK_L)
                                + (long long)tile * 96 + 4 * lane;
                #pragma unroll 8
                for (int r = 0; r < 32; ++r) {
                    float4 vv = *(const float4*)(ss + r * SPITCH + 4 * lane);
                    *(float4*)(out + sbase + (long long)r * (3 * CHUNK_L)) = vv;
                }
            }
            __syncwarp();
        }
    } else {
        // ---- generic scalar path (warp 0 / tail only) ----
        long long c = cb + lane;
        if (c < nchunks) {
            long long start = c * CHUNK_L;
            long long end = start + CHUNK_L; if (end > T) end = T;
            float s, v, i; long long t0;
            if (start <= WARM_W) {            // exact warm from t=0
                s = state0[0]; v = state0[1]; i = state0[2]; t0 = 0;
            } else {
                s = 0.f; v = 0.f; i = 0.f; t0 = start - WARM_W;
            }
            for (long long t = t0; t < start; ++t)
                lif_step(x[t], w, LI, LV, s, v, i);
            for (long long t = start; t < end; ++t) {
                lif_step(x[t], w, LI, LV, s, v, i);
                out[t] = s;
                if (write_states) {
                    long long b = (long long)T + 3 * t;
                    out[b] = s; out[b + 1] = v; out[b + 2] = i;
                }
            }
        }
    }
}

extern "C" void kernel_launch(void* const* d_in, const int* in_sizes, int n_in,
                              void* d_out, int out_size) {
    const float* x  = (const float*)d_in[0];   // (T, 1) float32
    const float* st = (const float*)d_in[1];   // (3, 1) float32 [s, v, i]
    const float* w  = (const float*)d_in[2];   // (1, 1) float32
    float* out = (float*)d_out;                // [outputs (T) | states (3T)]

    int T = in_sizes[0];
    int write_states = ((long long)out_size >= 4LL * T) ? 1 : 0;

    cudaFuncSetAttribute(lif_scan_kernel,
                         cudaFuncAttributeMaxDynamicSharedMemorySize, BLOCK_SMEM);

    long long nchunks = ((long long)T + CHUNK_L - 1) / CHUNK_L;
    long long nwarps  = (nchunks + LANES - 1) / LANES;
    int blocks = (int)((nwarps + WPB - 1) / WPB);
    lif_scan_kernel<<<blocks, NTHREADS, BLOCK_SMEM>>>(x, st, w, out, T, write_states);
}

// round 11
// speedup vs baseline: 2.9148x; 1.0469x over previous
#include <cuda_runtime.h>
#include <cuda_bf16.h>

// LIF scan, chunk-parallel with cold-start warm-up, coalesced SMEM staging,
// vectorized, predicate-carried spike reset (12-cyc serial chain).
//
//   i_t = LEAK_I*i_{t-1} + w*x_t
//   v_t = LEAK_V*v_{t-1}*(1-s_{t-1}) + i_t
//   s_t = (v_t - 1 > 0)        [ == (v_t > 1) exactly in f32 ]
//
// Reset as predicate: lv = spk ? 0 : LV*v. Reference computes (LV*v)*(1-s)
// which is exactly LV*v or +/-0; +/-0 + i == 0 + i in f32 -> identical bits.
// Warm-up W=128 from zeros: i converges at (6/7)^128 ~ 3e-9, spikes (~every 4
// steps) resync v bitwise (validated R8: rel_err 4.7e-6). Chunks with
// start <= W warm exactly from state0.
//
// R9 lesson: 32-float rows cannot satisfy both float4 alignment
// (pitch = 0 mod 4) and serial-loop LDS.128 conflict-freedom
// (2*pitch/4 odd) -> XPITCH=34 trapped on misaligned LDS.128.
// R10/R11 layout: 64-float chunk-rows, XPITCH=68 words:
//   - 68 = 0 mod 4  -> all float4 offsets 16B-aligned
//   - lane row-stride 68 -> bank quad = lane*17 = lane (mod 8): CF
//   - fill stores (row = q>>4, col = (q&15)*4): CF in every phase
// Warm rows lane, lane+1; main row lane+2 (two 32-step half-row tiles).
// (R10 bench was a broker infra failure; unchanged resubmit.)

#define CHUNK_L 64
#define WARM_W  128
#define LANES   32
#define WPB     4
#define NTHREADS (WPB * LANES)

#define WIN_FLOATS (LANES * CHUNK_L + WARM_W)      // 2176
#define WIN_ROWS   (WIN_FLOATS / 64)               // 34 rows of 64 floats
#define XPITCH 68                                  // 0 mod 4; lane*17 CF mod 8
#define X_WORDS (WIN_ROWS * XPITCH)                // 2312
#define OPITCH 36                                  // 0 mod 4; lane*9 CF mod 8
#define O_WORDS (LANES * OPITCH)                   // 1152
#define SPITCH 100                                 // 0 mod 4; lane*25 CF mod 8
#define S_WORDS (LANES * SPITCH)                   // 3200
#define WARP_WORDS (X_WORDS + O_WORDS + S_WORDS)   // 6664
#define BLOCK_SMEM (WARP_WORDS * WPB * 4)          // 106624 B -> 2 CTAs/SM

// Chain: v -> FSETP(4) -> FSEL(4) -> FADD(4) = 12 cyc/step; i-chain parallel.
__device__ __forceinline__ void lif_step(float xt, float w, float LI, float LV,
                                         bool& spk, float& v, float& i) {
    float wx = __fmul_rn(w, xt);
    i = __fadd_rn(__fmul_rn(LI, i), wx);
    float lv = __fmul_rn(LV, v);          // off-chain until FSEL
    lv = spk ? 0.0f : lv;                 // FSEL (pred-as-data)
    v = __fadd_rn(lv, i);
    spk = (v > 1.0f);                     // FSETP
}

__global__ void __launch_bounds__(NTHREADS, 2)
lif_scan_kernel(const float* __restrict__ x,
                const float* __restrict__ state0,
                const float* __restrict__ wptr,
                float* __restrict__ out,
                int T, int write_states) {
    extern __shared__ float sm[];
    const float LI = (float)(1.0 - 1.0 / 7.0);    // 6/7
    const float LV = (float)(1.0 - 1.0 / 10.0);   // 0.9

    const int lane = threadIdx.x & 31;
    const int warp = threadIdx.x >> 5;
    float* xs = sm + warp * WARP_WORDS;   // x window,     pitch 68 (64-float rows)
    float* os = xs + X_WORDS;             // outputs tile, pitch 36
    float* ss = os + O_WORDS;             // states tile,  pitch 100

    const long long nchunks = ((long long)T + CHUNK_L - 1) / CHUNK_L;
    const long long wid = (long long)blockIdx.x * WPB + warp;
    const long long cb  = wid * LANES;            // first chunk of this warp
    if (cb >= nchunks) return;                    // warp-uniform

    const long long B = cb * CHUNK_L - WARM_W;    // window base
    const float w = wptr[0];

    // Fast path: full interior warp (window + all 32 chunks in-bounds).
    const bool fastw = (B >= 0) && ((cb + LANES) * CHUNK_L <= (long long)T);

    if (fastw) {
        // ---- coalesced window fill: 17 LDG.128 rounds ----
        {
            const float4* g = (const float4*)(x + B);
            #pragma unroll
            for (int it = 0; it < WIN_FLOATS / 128; ++it) {
                int q = it * 32 + lane;
                float4 val = g[q];
                int row = q >> 4, col = (q & 15) * 4;   // 64-float rows
                *(float4*)(xs + row * XPITCH + col) = val;
            }
        }
        __syncwarp();

        bool spk = false;
        float v = 0.f, i = 0.f;

        // ---- warm-up: rows lane, lane+1 (128 steps), aligned CF LDS.128 ----
        #pragma unroll
        for (int r = 0; r < 2; ++r) {
            const float* p = xs + (lane + r) * XPITCH;
            #pragma unroll
            for (int jj = 0; jj < 64; jj += 4) {
                float4 q = *(const float4*)(p + jj);
                lif_step(q.x, w, LI, LV, spk, v, i);
                lif_step(q.y, w, LI, LV, spk, v, i);
                lif_step(q.z, w, LI, LV, spk, v, i);
                lif_step(q.w, w, LI, LV, spk, v, i);
            }
        }

        // ---- main: row lane+2, two 32-step half-row tiles ----
        const float* pm = xs + (lane + 2) * XPITCH;
        float* orow = os + lane * OPITCH;
        float* srow = ss + lane * SPITCH;
        #pragma unroll
        for (int tile = 0; tile < 2; ++tile) {
            #pragma unroll
            for (int jj = 0; jj < 32; jj += 4) {
                float4 q = *(const float4*)(pm + tile * 32 + jj);
                float4 o4, st0, st1, st2;
                float s;
                lif_step(q.x, w, LI, LV, spk, v, i); s = spk ? 1.f : 0.f;
                o4.x = s; st0.x = s; st0.y = v; st0.z = i;
                lif_step(q.y, w, LI, LV, spk, v, i); s = spk ? 1.f : 0.f;
                o4.y = s; st0.w = s; st1.x = v; st1.y = i;
                lif_step(q.z, w, LI, LV, spk, v, i); s = spk ? 1.f : 0.f;
                o4.z = s; st1.z = s; st1.w = v; st2.x = i;
                lif_step(q.w, w, LI, LV, spk, v, i); s = spk ? 1.f : 0.f;
                o4.w = s; st2.y = s; st2.z = v; st2.w = i;
                *(float4*)(orow + jj) = o4;
                float* sp = srow + 3 * jj;
                *(float4*)(sp)     = st0;
                *(float4*)(sp + 4) = st1;
                *(float4*)(sp + 8) = st2;
            }
            __syncwarp();

            // outputs flush: 8 STG.128 rounds (4 chunks per round, coalesced)
            {
                long long obase = cb * CHUNK_L + (long long)tile * 32;
                int sub = lane >> 3;          // 0..3
                int off = (lane & 7) * 4;     // 0..28
                #pragma unroll
                for (int g = 0; g < 8; ++g) {
                    int rr = g * 4 + sub;
                    float4 vv = *(const float4*)(os + rr * OPITCH + off);
                    *(float4*)(out + obase + (long long)rr * CHUNK_L + off) = vv;
                }
            }
            // states flush: 32 STG.128 rounds (24 active lanes, 96 floats/chunk)
            if (write_states && lane < 24) {
                long long sbase = (long long)T + cb * (3 * CHUNK_L)
                                + (long long)tile * 96 + 4 * lane;
                #pragma unroll 8
                for (int r = 0; r < 32; ++r) {
                    float4 vv = *(const float4*)(ss + r * SPITCH + 4 * lane);
                    *(float4*)(out + sbase + (long long)r * (3 * CHUNK_L)) = vv;
                }
            }
            __syncwarp();
        }
    } else {
        // ---- generic scalar path (warp 0 / tail only) ----
        long long c = cb + lane;
        if (c < nchunks) {
            long long start = c * CHUNK_L;
            long long end = start + CHUNK_L; if (end > T) end = T;
            bool spk; float v, i; long long t0;
            if (start <= WARM_W) {            // exact warm from t=0
                spk = (state0[0] != 0.0f); v = state0[1]; i = state0[2]; t0 = 0;
            } else {
                spk = false; v = 0.f; i = 0.f; t0 = start - WARM_W;
            }
            for (long long t = t0; t < start; ++t)
                lif_step(x[t], w, LI, LV, spk, v, i);
            for (long long t = start; t < end; ++t) {
                lif_step(x[t], w, LI, LV, spk, v, i);
                float s = spk ? 1.f : 0.f;
                out[t] = s;
                if (write_states) {
                    long long b = (long long)T + 3 * t;
                    out[b] = s; out[b + 1] = v; out[b + 2] = i;
                }
            }
        }
    }
}

extern "C" void kernel_launch(void* const* d_in, const int* in_sizes, int n_in,
                              void* d_out, int out_size) {
    const float* x  = (const float*)d_in[0];   // (T, 1) float32
    const float* st = (const float*)d_in[1];   // (3, 1) float32 [s, v, i]
    const float* w  = (const float*)d_in[2];   // (1, 1) float32
    float* out = (float*)d_out;                // [outputs (T) | states (3T)]

    int T = in_sizes[0];
    int write_states = ((long long)out_size >= 4LL * T) ? 1 : 0;

    cudaFuncSetAttribute(lif_scan_kernel,
                         cudaFuncAttributeMaxDynamicSharedMemorySize, BLOCK_SMEM);

    long long nchunks = ((long long)T + CHUNK_L - 1) / CHUNK_L;
    long long nwarps  = (nchunks + LANES - 1) / LANES;
    int blocks = (int)((nwarps + WPB - 1) / WPB);
    lif_scan_kernel<<<blocks, NTHREADS, BLOCK_SMEM>>>(x, st, w, out, T, write_states);
}